// round 3
// baseline (speedup 1.0000x reference)
#include <cuda_runtime.h>
#include <cstdint>

#define B_N 4096
#define H_N 3
#define K_N 32768
#define D_N 128

#define BM 128
#define BN 128
#define DK 32
#define KSPLIT 32
#define KN (K_N / KSPLIT)   /* 1024 codewords per block */
#define NCHUNK (KN / BN)    /* 8 */

#define AS_PAD 132          /* float4-aligned stores, conflict-free */
#define BS_PAD 33           /* scalar stores, conflict-free compute loads */
#define SMEM_BYTES ((BM * AS_PAD + BN * BS_PAD) * 4)

// scratch (no allocation allowed)
__device__ float g_resid[B_N * D_N];
__device__ float g_wnorm[H_N * K_N];   // FULL ||W_k||^2 (fp32)
__device__ float g_rnorm[B_N];         // ||resid_b||^2 (fp32), per current head
__device__ unsigned long long g_keys[B_N];

__device__ __forceinline__ unsigned int f2ord(float f) {
    unsigned int u = __float_as_uint(f);
    return (u & 0x80000000u) ? ~u : (u | 0x80000000u);
}

// XLA-GPU-style warp row-reduction of sum(x_i^2) over 128 contiguous floats:
// lane t handles elements t, t+32, t+64, t+96 (separate rounded mul, then
// rounded add — no fma), then shfl-down butterfly 16,8,4,2,1.
__device__ __forceinline__ float warp_sumsq_128(const float* __restrict__ x, int lane) {
    float acc = 0.f;
    #pragma unroll
    for (int i = 0; i < 4; ++i) {
        float v = x[lane + 32 * i];
        float p = __fmul_rn(v, v);
        acc = __fadd_rn(acc, p);
    }
    #pragma unroll
    for (int off = 16; off; off >>= 1)
        acc = __fadd_rn(acc, __shfl_down_sync(0xffffffffu, acc, off));
    return acc;  // valid in lane 0
}

// ---------------------------------------------------------------------------
// init: resid = inputs, loss = 0, quantized = 0, keys = 0
__global__ void hrq_init_kernel(const float* __restrict__ inp, float* __restrict__ out) {
    int i = blockIdx.x * blockDim.x + threadIdx.x;
    if (i < B_N * D_N) {
        float v = inp[i];
        g_resid[i] = v;
        out[B_N + i] = 0.f;          // quantized
    }
    if (i < B_N) {
        out[i] = 0.f;                // loss
        g_keys[i] = 0ull;
    }
}

// ---------------------------------------------------------------------------
// wnorm: g_wnorm[h*K + k] = sum_d W[h][k][d]^2  (one warp per row)
__global__ void hrq_wnorm_kernel(const float* __restrict__ emb) {
    int gw   = (blockIdx.x * blockDim.x + threadIdx.x) >> 5;
    int lane = threadIdx.x & 31;
    if (gw >= H_N * K_N) return;
    float s = warp_sumsq_128(emb + (size_t)gw * D_N, lane);
    if (lane == 0) g_wnorm[gw] = s;
}

// ---------------------------------------------------------------------------
// rnorm: g_rnorm[b] = sum_d resid[b][d]^2  (one warp per row)
__global__ void hrq_rnorm_kernel() {
    int gw   = (blockIdx.x * blockDim.x + threadIdx.x) >> 5;
    int lane = threadIdx.x & 31;
    if (gw >= B_N) return;
    float s = warp_sumsq_128(g_resid + (size_t)gw * D_N, lane);
    if (lane == 0) g_rnorm[gw] = s;
}

// ---------------------------------------------------------------------------
// score: per-row argmin over this block's K-slice of
//   t_k = fl( fl(R_b + ||W_k||^2) - 2*dot_k )     (ref: argmax of -t_k)
// with ties -> lowest k; reduced into g_keys[b] via atomicMax on packed keys.
__global__ void __launch_bounds__(256, 2)
hrq_score_kernel(const float* __restrict__ emb, int h) {
    extern __shared__ float smem[];
    float* As = smem;                    // [BM][AS_PAD]
    float* Bs = smem + BM * AS_PAD;      // [BN][BS_PAD]

    const float* __restrict__ W  = emb + (size_t)h * K_N * D_N;
    const float* __restrict__ hw = g_wnorm + (size_t)h * K_N;

    int tid = threadIdx.x;
    int tx  = tid & 15;                  // column group
    int ty  = tid >> 4;                  // row group
    int rowBase = blockIdx.x * BM;
    int kBase   = blockIdx.y * KN;

    // load full resid tile [BM][D_N] once (persistent)
    {
        int lane = tid & 31, w = tid >> 5;
        #pragma unroll
        for (int it = 0; it < 16; ++it) {
            int r = w + (it << 3);
            float4 v = *reinterpret_cast<const float4*>(
                &g_resid[(size_t)(rowBase + r) * D_N + lane * 4]);
            *reinterpret_cast<float4*>(&As[r * AS_PAD + lane * 4]) = v;
        }
    }

    // per-row ||r||^2
    float Rreg[8];
    #pragma unroll
    for (int i = 0; i < 8; ++i)
        Rreg[i] = g_rnorm[rowBase + ty + (i << 4)];

    float bestS[8];
    int   bestI[8];
    #pragma unroll
    for (int i = 0; i < 8; ++i) { bestS[i] = -3.4e38f; bestI[i] = 0; }

    for (int ch = 0; ch < NCHUNK; ++ch) {
        int cwBase = kBase + ch * BN;

        float acc[8][8];
        #pragma unroll
        for (int i = 0; i < 8; ++i)
            #pragma unroll
            for (int j = 0; j < 8; ++j) acc[i][j] = 0.f;

        #pragma unroll
        for (int dc = 0; dc < D_N / DK; ++dc) {
            __syncthreads();
            // stage W chunk: 128 codewords x 32 dims
            {
                int d4 = tid & 7;
                int c0 = tid >> 3;
                #pragma unroll
                for (int it = 0; it < 4; ++it) {
                    int c = c0 + (it << 5);
                    float4 v = *reinterpret_cast<const float4*>(
                        &W[(size_t)(cwBase + c) * D_N + dc * DK + d4 * 4]);
                    float* dst = &Bs[c * BS_PAD + d4 * 4];
                    dst[0] = v.x; dst[1] = v.y; dst[2] = v.z; dst[3] = v.w;
                }
            }
            __syncthreads();

            // sequential ascending-d fp32 fma accumulation (cublas sgemm order)
            #pragma unroll
            for (int dd = 0; dd < DK; ++dd) {
                int d = dc * DK + dd;
                float a[8], b[8];
                #pragma unroll
                for (int i = 0; i < 8; ++i) a[i] = As[(ty + (i << 4)) * AS_PAD + d];
                #pragma unroll
                for (int j = 0; j < 8; ++j) b[j] = Bs[(tx + (j << 4)) * BS_PAD + dd];
                #pragma unroll
                for (int i = 0; i < 8; ++i)
                    #pragma unroll
                    for (int j = 0; j < 8; ++j)
                        acc[i][j] = fmaf(a[i], b[j], acc[i][j]);
            }
        }

        // fold into running per-row best, replicating the reference's fp32
        // rounding: t = fl(fl(R + wn) - 2*dot); maximize s = -t.
        // k ascends with j and ch, so strict > keeps the first occurrence of
        // the max (matching jnp.argmax tie-breaking).
        #pragma unroll
        for (int j = 0; j < 8; ++j) {
            int k = cwBase + tx + (j << 4);
            float wn = __ldg(&hw[k]);
            #pragma unroll
            for (int i = 0; i < 8; ++i) {
                float t1 = __fadd_rn(Rreg[i], wn);
                float t  = __fsub_rn(t1, 2.0f * acc[i][j]);
                float s  = -t;
                if (s > bestS[i]) { bestS[i] = s; bestI[i] = k; }
            }
        }
    }

    // reduce across the 16 column-group lanes (xor stays within half-warp),
    // then one atomicMax per row. Key packs (ordered score, 0xFFFFFFFF - k)
    // so equal scores resolve to the smallest k.
    #pragma unroll
    for (int i = 0; i < 8; ++i) {
        unsigned long long key =
            ((unsigned long long)f2ord(bestS[i]) << 32) |
            (unsigned long long)(0xFFFFFFFFu - (unsigned)bestI[i]);
        #pragma unroll
        for (int off = 8; off; off >>= 1) {
            unsigned long long o = __shfl_xor_sync(0xffffffffu, key, off);
            if (o > key) key = o;
        }
        if (tx == 0)
            atomicMax(&g_keys[rowBase + ty + (i << 4)], key);
    }
}

// ---------------------------------------------------------------------------
// update: decode winner, write code, resid -= q, quantized += q, reset key,
// and compute next head's ||resid||^2 (same reduction pattern as rnorm).
__global__ void hrq_update_kernel(const float* __restrict__ emb,
                                  float* __restrict__ out, int h) {
    int b = blockIdx.x;
    int d = threadIdx.x;
    unsigned long long key = g_keys[b];
    int k = (int)(0xFFFFFFFFu - (unsigned)(key & 0xFFFFFFFFull));
    float q = emb[((size_t)h * K_N + (size_t)k) * D_N + d];
    float r = g_resid[b * D_N + d] - q;
    g_resid[b * D_N + d] = r;
    out[B_N + b * D_N + d] += q;
    __syncthreads();                       // resid fully written, key consumed
    if (d < 32) {                          // warp 0: new ||r||^2
        float s = warp_sumsq_128(g_resid + (size_t)b * D_N, d);
        if (d == 0) {
            g_rnorm[b] = s;
            out[B_N + B_N * D_N + b * H_N + h] = (float)k;
            g_keys[b] = 0ull;              // ready for next head
        }
    }
}

// ---------------------------------------------------------------------------
extern "C" void kernel_launch(void* const* d_in, const int* in_sizes, int n_in,
                              void* d_out, int out_size) {
    const float* inputs = (const float*)d_in[0];
    const float* emb    = (const float*)d_in[1];
    if (n_in >= 2 && in_sizes[0] != B_N * D_N) {   // defensive: order swap
        inputs = (const float*)d_in[1];
        emb    = (const float*)d_in[0];
    }
    float* out = (float*)d_out;

    cudaFuncSetAttribute(hrq_score_kernel,
                         cudaFuncAttributeMaxDynamicSharedMemorySize, SMEM_BYTES);

    hrq_init_kernel<<<(B_N * D_N + 255) / 256, 256>>>(inputs, out);
    hrq_wnorm_kernel<<<(H_N * K_N * 32 + 255) / 256, 256>>>(emb);
    hrq_rnorm_kernel<<<(B_N * 32 + 255) / 256, 256>>>();

    dim3 sgrid(B_N / BM, KSPLIT);
    for (int h = 0; h < H_N; ++h) {
        hrq_score_kernel<<<sgrid, 256, SMEM_BYTES>>>(emb, h);
        hrq_update_kernel<<<B_N, D_N>>>(emb, out, h);
    }
}

// round 4
// speedup vs baseline: 2.3209x; 2.3209x over previous
#include <cuda_runtime.h>
#include <cuda_bf16.h>
#include <cstdint>

#define B_N 4096
#define H_N 3
#define K_N 32768
#define D_N 128

#define CAP 256            /* candidate list capacity per row */

/* coarse kernel tiling */
#define CBM 128            /* rows per block */
#define KSPLIT2 16         /* k-slices */
#define KN2 (K_N / KSPLIT2)    /* 2048 codewords per block */
#define CBN 128            /* codewords per chunk */
#define NCH (KN2 / CBN)        /* 16 chunks */
#define PITCHW 68          /* smem row pitch in 32-bit words (128 halves + 8 pad) */

#define CSMEM_BYTES ((2 * CBM * PITCHW + 128 + 128) * 4)

// ------------------------------ scratch ------------------------------------
__device__ float           g_resid[B_N * D_N];
__device__ __nv_bfloat16   g_resid16[B_N * D_N];
__device__ __nv_bfloat16   g_emb16[H_N * K_N * D_N];
__device__ float           g_wnorm[H_N * K_N];     // ||W_k||^2 fp32
__device__ unsigned        g_wnmax[H_N];           // max_k ||W_k||^2 (float bits)
__device__ float           g_rnorm[B_N];           // ||resid_b||^2 fp32
__device__ int             g_cand[B_N * CAP];
__device__ int             g_ccnt[B_N];

__device__ __forceinline__ unsigned f2ord(float f) {
    unsigned u = __float_as_uint(f);
    return (u & 0x80000000u) ? ~u : (u | 0x80000000u);
}
__device__ __forceinline__ float ord2f(unsigned u) {
    return (u & 0x80000000u) ? __uint_as_float(u & 0x7FFFFFFFu)
                             : __uint_as_float(~u);
}

// XLA-GPU-style warp reduction of sum(x^2) over 128 floats (bit-exact w/ ref)
__device__ __forceinline__ float warp_sumsq_128(const float* __restrict__ x, int lane) {
    float acc = 0.f;
    #pragma unroll
    for (int i = 0; i < 4; ++i) {
        float v = x[lane + 32 * i];
        acc = __fadd_rn(acc, __fmul_rn(v, v));
    }
    #pragma unroll
    for (int off = 16; off; off >>= 1)
        acc = __fadd_rn(acc, __shfl_down_sync(0xffffffffu, acc, off));
    return acc;
}

// ---------------------------------------------------------------------------
__global__ void hrq_init_kernel(const float* __restrict__ inp, float* __restrict__ out) {
    int i = blockIdx.x * blockDim.x + threadIdx.x;
    if (i < B_N * D_N) {
        float v = inp[i];
        g_resid[i]   = v;
        g_resid16[i] = __float2bfloat16(v);
        out[B_N + i] = 0.f;                 // quantized
    }
    if (i < B_N) {
        out[i] = 0.f;                       // loss
        g_ccnt[i] = 0;
    }
    if (i < H_N) g_wnmax[i] = 0u;
}

__global__ void hrq_emb2bf_kernel(const float* __restrict__ emb) {
    int i = blockIdx.x * blockDim.x + threadIdx.x;
    if (i < H_N * K_N * D_N) g_emb16[i] = __float2bfloat16(emb[i]);
}

// wnorm + per-head max
__global__ void hrq_wnorm_kernel(const float* __restrict__ emb) {
    int gw   = (blockIdx.x * blockDim.x + threadIdx.x) >> 5;
    int lane = threadIdx.x & 31;
    if (gw >= H_N * K_N) return;
    float s = warp_sumsq_128(emb + (size_t)gw * D_N, lane);
    if (lane == 0) {
        g_wnorm[gw] = s;
        atomicMax(&g_wnmax[gw / K_N], __float_as_uint(s));  // s >= 0
    }
}

__global__ void hrq_rnorm_kernel() {
    int gw   = (blockIdx.x * blockDim.x + threadIdx.x) >> 5;
    int lane = threadIdx.x & 31;
    if (gw >= B_N) return;
    float s = warp_sumsq_128(g_resid + (size_t)gw * D_N, lane);
    if (lane == 0) g_rnorm[gw] = s;
}

// ---------------------------------------------------------------------------
// coarse: bf16 mma.sync scoring; emit candidates within delta of running
// per-row block best. delta is a hard bound on coarse-vs-exact error, so the
// exact winner is always emitted.
__device__ __forceinline__ void mma16816(float c[4], const unsigned a[4],
                                         unsigned b0, unsigned b1) {
    asm("mma.sync.aligned.m16n8k16.row.col.f32.bf16.bf16.f32 "
        "{%0,%1,%2,%3},{%4,%5,%6,%7},{%8,%9},{%0,%1,%2,%3};"
        : "+f"(c[0]), "+f"(c[1]), "+f"(c[2]), "+f"(c[3])
        : "r"(a[0]), "r"(a[1]), "r"(a[2]), "r"(a[3]), "r"(b0), "r"(b1));
}

// copy a contiguous 32KB (128 rows x 256B) bf16 tile into padded smem
__device__ __forceinline__ void copy_tile(uint32_t* dst, const uint2* __restrict__ src,
                                          int tid) {
    #pragma unroll
    for (int j = 0; j < 16; ++j) {
        int i = tid + 256 * j;                 // uint2 index, 4096 total
        uint2 v = src[i];
        int row = i >> 5;                      // 32 uint2 per row
        int dw  = row * PITCHW + ((i & 31) << 1);
        *reinterpret_cast<uint2*>(dst + dw) = v;
    }
}

__global__ void __launch_bounds__(256, 2)
hrq_coarse_kernel(int h) {
    extern __shared__ uint32_t smw[];
    uint32_t* Aw = smw;                        // [128][PITCHW]
    uint32_t* Bw = smw + CBM * PITCHW;         // [128][PITCHW]
    float*    wns = (float*)(Bw + CBM * PITCHW);       // [128]
    unsigned* rowbest = (unsigned*)(wns + 128);        // [128]

    int tid  = threadIdx.x;
    int lane = tid & 31;
    int wid  = tid >> 5;
    int wm   = wid & 3;                        // 4 M-groups of 32 rows
    int wn   = wid >> 2;                       // 2 N-groups of 64 cols
    int q4   = lane & 3;                       // quad index
    int l4   = lane >> 2;                      // 0..7

    int rowBase = blockIdx.x * CBM;
    int kBase   = blockIdx.y * KN2;

    // persistent A tile (resid bf16)
    copy_tile(Aw, (const uint2*)(g_resid16 + (size_t)rowBase * D_N), tid);
    if (tid < 128) rowbest[tid] = 0u;

    // per-lane rows & deltas
    int rloc[4];
    float delta[4];
    {
        float wnmax = __uint_as_float(g_wnmax[h]);
        #pragma unroll
        for (int rr = 0; rr < 4; ++rr) {
            rloc[rr] = wm * 32 + (rr & 1) * 16 + ((rr >> 1) << 3) + l4; // +0,+16,+8,+24
        }
        // order as used below: rr = mt*2 + hi  -> row = wm*32 + mt*16 + hi*8 + l4
        rloc[0] = wm * 32 + 0 * 16 + 0 + l4;
        rloc[1] = wm * 32 + 0 * 16 + 8 + l4;
        rloc[2] = wm * 32 + 1 * 16 + 0 + l4;
        rloc[3] = wm * 32 + 1 * 16 + 8 + l4;
        #pragma unroll
        for (int rr = 0; rr < 4; ++rr) {
            float R = g_rnorm[rowBase + rloc[rr]];
            delta[rr] = 0.02f * sqrtf(R * wnmax);
        }
    }
    __syncthreads();

    const uint2* Wsrc = (const uint2*)(g_emb16 + ((size_t)h * K_N + kBase) * D_N);
    const float* hw   = g_wnorm + (size_t)h * K_N;

    for (int ch = 0; ch < NCH; ++ch) {
        // stage B tile + wnorms
        copy_tile(Bw, Wsrc + (size_t)ch * (CBN * D_N / 4), tid);
        if (tid < 128) wns[tid] = hw[kBase + ch * CBN + tid];
        __syncthreads();

        float acc[2][8][4];
        #pragma unroll
        for (int mt = 0; mt < 2; ++mt)
            #pragma unroll
            for (int nt = 0; nt < 8; ++nt)
                #pragma unroll
                for (int c = 0; c < 4; ++c) acc[mt][nt][c] = 0.f;

        #pragma unroll
        for (int kt = 0; kt < 8; ++kt) {
            unsigned a[2][4];
            #pragma unroll
            for (int mt = 0; mt < 2; ++mt) {
                int r0 = wm * 32 + mt * 16 + l4;
                a[mt][0] = Aw[r0 * PITCHW + kt * 8 + q4];
                a[mt][1] = Aw[(r0 + 8) * PITCHW + kt * 8 + q4];
                a[mt][2] = Aw[r0 * PITCHW + kt * 8 + q4 + 4];
                a[mt][3] = Aw[(r0 + 8) * PITCHW + kt * 8 + q4 + 4];
            }
            #pragma unroll
            for (int nt = 0; nt < 8; ++nt) {
                int n0 = wn * 64 + nt * 8 + l4;
                unsigned b0 = Bw[n0 * PITCHW + kt * 8 + q4];
                unsigned b1 = Bw[n0 * PITCHW + kt * 8 + q4 + 4];
                mma16816(acc[0][nt], a[0], b0, b1);
                mma16816(acc[1][nt], a[1], b0, b1);
            }
        }

        // fold: s = 2*acc - wn (in place), track per-lane row maxes
        float mx[4] = {-3.4e38f, -3.4e38f, -3.4e38f, -3.4e38f};
        #pragma unroll
        for (int mt = 0; mt < 2; ++mt)
            #pragma unroll
            for (int nt = 0; nt < 8; ++nt) {
                float w0 = wns[wn * 64 + nt * 8 + 2 * q4];
                float w1 = wns[wn * 64 + nt * 8 + 2 * q4 + 1];
                #pragma unroll
                for (int c = 0; c < 4; ++c) {
                    float s = fmaf(2.f, acc[mt][nt][c], -((c & 1) ? w1 : w0));
                    acc[mt][nt][c] = s;
                    int rr = mt * 2 + (c >> 1);
                    if (s > mx[rr]) mx[rr] = s;
                }
            }
        #pragma unroll
        for (int rr = 0; rr < 4; ++rr)
            atomicMax(&rowbest[rloc[rr]], f2ord(mx[rr]));
        __syncthreads();

        // emit candidates above (running best - delta)
        float thr[4];
        #pragma unroll
        for (int rr = 0; rr < 4; ++rr)
            thr[rr] = ord2f(rowbest[rloc[rr]]) - delta[rr];

        int kCh = kBase + ch * CBN;
        #pragma unroll
        for (int mt = 0; mt < 2; ++mt)
            #pragma unroll
            for (int nt = 0; nt < 8; ++nt)
                #pragma unroll
                for (int c = 0; c < 4; ++c) {
                    int rr = mt * 2 + (c >> 1);
                    if (acc[mt][nt][c] >= thr[rr]) {
                        int row = rowBase + rloc[rr];
                        int k   = kCh + wn * 64 + nt * 8 + 2 * q4 + (c & 1);
                        int idx = atomicAdd(&g_ccnt[row], 1);
                        if (idx < CAP) g_cand[row * CAP + idx] = k;
                    }
                }
        __syncthreads();   // emissions done before Bs overwrite
    }
}

// ---------------------------------------------------------------------------
// rescore (exact, bit-identical to reference path) + update, fused.
__global__ void hrq_rescore_update_kernel(const float* __restrict__ emb,
                                          float* __restrict__ out, int h) {
    __shared__ unsigned long long wkey[4];
    __shared__ int swin;

    int b = blockIdx.x;
    int t = threadIdx.x;          // 128 threads
    int lane = t & 31, w = t >> 5;

    int n = g_ccnt[b]; if (n > CAP) n = CAP; if (n < 1) n = 1;
    float R = g_rnorm[b];
    const float* __restrict__ r = g_resid + (size_t)b * D_N;
    const float* __restrict__ Wh = emb + (size_t)h * K_N * D_N;
    const float* __restrict__ hw = g_wnorm + (size_t)h * K_N;

    unsigned long long best = 0ull;
    for (int i = t; i < n; i += 128) {
        int k = g_cand[b * CAP + i];
        const float* wrow = Wh + (size_t)k * D_N;
        float acc = 0.f;
        #pragma unroll 16
        for (int d = 0; d < D_N; ++d)               // sequential ascending d
            acc = fmaf(r[d], wrow[d], acc);
        float tt = __fsub_rn(__fadd_rn(R, hw[k]), 2.0f * acc);
        unsigned long long key =
            ((unsigned long long)f2ord(-tt) << 32) |
            (unsigned long long)(0xFFFFFFFFu - (unsigned)k);
        if (key > best) best = key;
    }
    #pragma unroll
    for (int off = 16; off; off >>= 1) {
        unsigned long long o = __shfl_xor_sync(0xffffffffu, best, off);
        if (o > best) best = o;
    }
    if (lane == 0) wkey[w] = best;
    __syncthreads();
    if (t == 0) {
        unsigned long long m = wkey[0];
        for (int i = 1; i < 4; ++i) if (wkey[i] > m) m = wkey[i];
        swin = (int)(0xFFFFFFFFu - (unsigned)(m & 0xFFFFFFFFull));
    }
    __syncthreads();

    int k = swin;
    float q  = Wh[(size_t)k * D_N + t];
    float nr = g_resid[b * D_N + t] - q;
    g_resid[b * D_N + t]   = nr;
    g_resid16[b * D_N + t] = __float2bfloat16(nr);
    out[B_N + b * D_N + t] += q;
    __syncthreads();
    if (t < 32) {
        float s = warp_sumsq_128(g_resid + (size_t)b * D_N, t);
        if (t == 0) {
            g_rnorm[b] = s;
            out[B_N + B_N * D_N + b * H_N + h] = (float)k;
            g_ccnt[b] = 0;
        }
    }
}

// ---------------------------------------------------------------------------
extern "C" void kernel_launch(void* const* d_in, const int* in_sizes, int n_in,
                              void* d_out, int out_size) {
    const float* inputs = (const float*)d_in[0];
    const float* emb    = (const float*)d_in[1];
    if (n_in >= 2 && in_sizes[0] != B_N * D_N) {
        inputs = (const float*)d_in[1];
        emb    = (const float*)d_in[0];
    }
    float* out = (float*)d_out;

    cudaFuncSetAttribute(hrq_coarse_kernel,
                         cudaFuncAttributeMaxDynamicSharedMemorySize, CSMEM_BYTES);

    hrq_init_kernel<<<(B_N * D_N + 255) / 256, 256>>>(inputs, out);
    hrq_emb2bf_kernel<<<(H_N * K_N * D_N + 255) / 256, 256>>>(emb);
    hrq_wnorm_kernel<<<(H_N * K_N * 32 + 255) / 256, 256>>>(emb);
    hrq_rnorm_kernel<<<(B_N * 32 + 255) / 256, 256>>>();

    dim3 cgrid(B_N / CBM, KSPLIT2);
    for (int h = 0; h < H_N; ++h) {
        hrq_coarse_kernel<<<cgrid, 256, CSMEM_BYTES>>>(h);
        hrq_rescore_update_kernel<<<B_N, 128>>>(emb, out, h);
    }
}

// round 6
// speedup vs baseline: 3.0143x; 1.2988x over previous
#include <cuda_runtime.h>
#include <cuda_bf16.h>
#include <cstdint>

#define B_N 4096
#define H_N 3
#define K_N 32768
#define D_N 128

#define CAP 256

/* coarse tiling */
#define CBM 128                 /* rows per CTA */
#define CBN 64                  /* codewords per chunk */
#define KSPLIT2 16
#define KN2 (K_N / KSPLIT2)     /* 2048 codewords per CTA */
#define NCH (KN2 / CBN)         /* 32 chunks */

#define APITCH 272              /* bytes per smem A row: 256 + 16 pad */
#define BPITCH 272

/* smem layout (bytes) */
#define SM_A       0            /* 128 * 272 = 34816 */
#define SM_B0      34816        /* 64 * 272 = 17408 */
#define SM_B1      52224
#define SM_WNS0    69632        /* 64 floats */
#define SM_WNS1    69888
#define SM_ROWBEST 70144        /* 128 * 4 */
#define SM_TOTAL   70656

// ------------------------------ scratch ------------------------------------
__device__ float           g_resid[B_N * D_N];
__device__ __nv_bfloat16   g_resid16[B_N * D_N];
__device__ __nv_bfloat16   g_emb16[H_N * K_N * D_N];
__device__ float           g_wnorm[H_N * K_N];
__device__ unsigned        g_wnmax[H_N];
__device__ float           g_rnorm[B_N];
__device__ int             g_cand[B_N * CAP];
__device__ int             g_ccnt[B_N];

// ------------------------------ helpers ------------------------------------
__device__ __forceinline__ unsigned f2ord(float f) {
    unsigned u = __float_as_uint(f);
    return (u & 0x80000000u) ? ~u : (u | 0x80000000u);
}
__device__ __forceinline__ float ord2f(unsigned u) {
    return (u & 0x80000000u) ? __uint_as_float(u & 0x7FFFFFFFu)
                             : __uint_as_float(~u);
}
__device__ __forceinline__ uint32_t smem_u32(const void* p) {
    uint32_t a;
    asm("{ .reg .u64 t; cvta.to.shared.u64 t, %1; cvt.u32.u64 %0, t; }"
        : "=r"(a) : "l"(p));
    return a;
}
__device__ __forceinline__ void cp16(uint32_t dst, const void* src) {
    asm volatile("cp.async.ca.shared.global [%0], [%1], 16;"
                 :: "r"(dst), "l"(__cvta_generic_to_global(src)) : "memory");
}
#define CP_COMMIT() asm volatile("cp.async.commit_group;" ::: "memory")
#define CP_WAIT0()  asm volatile("cp.async.wait_group 0;" ::: "memory")

__device__ __forceinline__ void ldmx4(unsigned r[4], uint32_t addr) {
    asm volatile("ldmatrix.sync.aligned.m8n8.x4.shared.b16 {%0,%1,%2,%3}, [%4];"
                 : "=r"(r[0]), "=r"(r[1]), "=r"(r[2]), "=r"(r[3]) : "r"(addr));
}
__device__ __forceinline__ void mma16816(float c[4], const unsigned a[4],
                                         unsigned b0, unsigned b1) {
    asm("mma.sync.aligned.m16n8k16.row.col.f32.bf16.bf16.f32 "
        "{%0,%1,%2,%3},{%4,%5,%6,%7},{%8,%9},{%0,%1,%2,%3};"
        : "+f"(c[0]), "+f"(c[1]), "+f"(c[2]), "+f"(c[3])
        : "r"(a[0]), "r"(a[1]), "r"(a[2]), "r"(a[3]), "r"(b0), "r"(b1));
}

// XLA-GPU-style warp reduction of sum(x^2) over 128 floats (bit-exact w/ ref)
__device__ __forceinline__ float warp_sumsq_128(const float* __restrict__ x, int lane) {
    float acc = 0.f;
    #pragma unroll
    for (int i = 0; i < 4; ++i) {
        float v = x[lane + 32 * i];
        acc = __fadd_rn(acc, __fmul_rn(v, v));
    }
    #pragma unroll
    for (int off = 16; off; off >>= 1)
        acc = __fadd_rn(acc, __shfl_down_sync(0xffffffffu, acc, off));
    return acc;
}

// ---------------------------------------------------------------------------
__global__ void hrq_init_kernel(const float* __restrict__ inp, float* __restrict__ out) {
    int i = blockIdx.x * blockDim.x + threadIdx.x;
    if (i < B_N * D_N) {
        float v = inp[i];
        g_resid[i]   = v;
        g_resid16[i] = __float2bfloat16(v);
        out[B_N + i] = 0.f;
    }
    if (i < B_N) { out[i] = 0.f; g_ccnt[i] = 0; }
    if (i < H_N) g_wnmax[i] = 0u;
}

// emb -> bf16 copy + wnorm (+ per-head max), one warp per codeword
__global__ void hrq_prep_kernel(const float* __restrict__ emb) {
    int gw   = (blockIdx.x * blockDim.x + threadIdx.x) >> 5;
    int lane = threadIdx.x & 31;
    if (gw >= H_N * K_N) return;
    const float* x = emb + (size_t)gw * D_N;
    __nv_bfloat16* y = g_emb16 + (size_t)gw * D_N;
    float acc = 0.f;
    #pragma unroll
    for (int i = 0; i < 4; ++i) {
        float v = x[lane + 32 * i];
        y[lane + 32 * i] = __float2bfloat16(v);
        acc = __fadd_rn(acc, __fmul_rn(v, v));
    }
    #pragma unroll
    for (int off = 16; off; off >>= 1)
        acc = __fadd_rn(acc, __shfl_down_sync(0xffffffffu, acc, off));
    if (lane == 0) {
        g_wnorm[gw] = acc;
        atomicMax(&g_wnmax[gw / K_N], __float_as_uint(acc));
    }
}

__global__ void hrq_rnorm_kernel() {
    int gw   = (blockIdx.x * blockDim.x + threadIdx.x) >> 5;
    int lane = threadIdx.x & 31;
    if (gw >= B_N) return;
    float s = warp_sumsq_128(g_resid + (size_t)gw * D_N, lane);
    if (lane == 0) g_rnorm[gw] = s;
}

// ---------------------------------------------------------------------------
// coarse: bf16 mma.sync scoring via ldmatrix + cp.async double-buffered B.
// Emits every codeword within delta of the (relaxed) running per-row best;
// delta = 2.5x the hard bf16 rounding bound, so the exact winner is always
// emitted (stale/partial thresholds only ADD candidates).
__global__ void __launch_bounds__(256, 2)
hrq_coarse_kernel(int h) {
    extern __shared__ char smem[];
    const uint32_t sb = smem_u32(smem);
    unsigned* rowbest = (unsigned*)(smem + SM_ROWBEST);

    const int tid  = threadIdx.x;
    const int lane = tid & 31;
    const int wid  = tid >> 5;
    const int wm   = wid & 3;           /* 4 row groups of 32 */
    const int wn   = wid >> 2;          /* 2 col groups of 32 */
    const int g4   = lane >> 2;         /* 0..7 */
    const int q4   = lane & 3;

    const int rowBase = blockIdx.x * CBM;
    const int kBase   = blockIdx.y * KN2;

    if (tid < 128) rowbest[tid] = 0u;

    const __nv_bfloat16* Wh = g_emb16 + ((size_t)h * K_N + kBase) * D_N;
    const float* hwg        = g_wnorm + (size_t)h * K_N + kBase;

    // stage A (128x128 bf16 -> padded smem rows)
    {
        const char* src = (const char*)(g_resid16 + (size_t)rowBase * D_N);
        #pragma unroll
        for (int j = 0; j < 8; ++j) {
            int i = tid + 256 * j, row = i >> 4, c = i & 15;
            cp16(sb + SM_A + row * APITCH + c * 16, src + i * 16);
        }
    }
    // stage B chunk 0 + wns0
    {
        const char* src = (const char*)Wh;
        #pragma unroll
        for (int j = 0; j < 4; ++j) {
            int i = tid + 256 * j, row = i >> 4, c = i & 15;
            cp16(sb + SM_B0 + row * BPITCH + c * 16, src + i * 16);
        }
        if (tid < 16) cp16(sb + SM_WNS0 + tid * 16, (const char*)hwg + tid * 16);
    }
    CP_COMMIT();

    // per-thread rows & deltas (4 result rows per thread)
    int rloc[4];
    float delta[4];
    {
        float wnmax = __uint_as_float(g_wnmax[h]);
        #pragma unroll
        for (int mt = 0; mt < 2; ++mt)
            #pragma unroll
            for (int hi = 0; hi < 2; ++hi) {
                int rr = mt * 2 + hi;
                rloc[rr] = wm * 32 + mt * 16 + hi * 8 + g4;
                float R = g_rnorm[rowBase + rloc[rr]];
                delta[rr] = 0.02f * sqrtf(R * wnmax);
            }
    }
    CP_WAIT0();
    __syncthreads();

    // ldmatrix lane-address components
    const int aRow = lane & 15;
    const int aCol = (lane >> 4) << 3;                    /* 0 or 8 */
    const int bN   = ((lane >= 16) ? 8 : 0) + (lane & 7);
    const int bK   = ((lane >> 3) & 1) << 3;

    for (int ch = 0; ch < NCH; ++ch) {
        const int cur = ch & 1;
        if (ch + 1 < NCH) {   // prefetch next B chunk into the other buffer
            const char* src = (const char*)(Wh + (size_t)(ch + 1) * CBN * D_N);
            uint32_t bdst = sb + (cur ? SM_B0 : SM_B1);
            #pragma unroll
            for (int j = 0; j < 4; ++j) {
                int i = tid + 256 * j, row = i >> 4, c = i & 15;
                cp16(bdst + row * BPITCH + c * 16, src + i * 16);
            }
            if (tid < 16)
                cp16(sb + (cur ? SM_WNS0 : SM_WNS1) + tid * 16,
                     (const char*)(hwg + (ch + 1) * CBN) + tid * 16);
            CP_COMMIT();
        }

        const uint32_t abase = sb + SM_A;
        const uint32_t bbase = sb + (cur ? SM_B1 : SM_B0);
        const float* wns = (const float*)(smem + (cur ? SM_WNS1 : SM_WNS0));

        float acc[2][4][4];
        #pragma unroll
        for (int mt = 0; mt < 2; ++mt)
            #pragma unroll
            for (int nt = 0; nt < 4; ++nt)
                #pragma unroll
                for (int c = 0; c < 4; ++c) acc[mt][nt][c] = 0.f;

        #pragma unroll
        for (int kt = 0; kt < 8; ++kt) {
            unsigned a0[4], a1[4], b01[4], b23[4];
            ldmx4(a0, abase + (wm * 32 +      aRow) * APITCH + (kt * 16 + aCol) * 2);
            ldmx4(a1, abase + (wm * 32 + 16 + aRow) * APITCH + (kt * 16 + aCol) * 2);
            ldmx4(b01, bbase + (wn * 32 +      bN) * BPITCH + (kt * 16 + bK) * 2);
            ldmx4(b23, bbase + (wn * 32 + 16 + bN) * BPITCH + (kt * 16 + bK) * 2);
            mma16816(acc[0][0], a0, b01[0], b01[1]);
            mma16816(acc[0][1], a0, b01[2], b01[3]);
            mma16816(acc[0][2], a0, b23[0], b23[1]);
            mma16816(acc[0][3], a0, b23[2], b23[3]);
            mma16816(acc[1][0], a1, b01[0], b01[1]);
            mma16816(acc[1][1], a1, b01[2], b01[3]);
            mma16816(acc[1][2], a1, b23[0], b23[1]);
            mma16816(acc[1][3], a1, b23[2], b23[3]);
        }

        // per-row maxes of s = 2*acc - wn
        float mx[4] = { -3.4e38f, -3.4e38f, -3.4e38f, -3.4e38f };
        #pragma unroll
        for (int mt = 0; mt < 2; ++mt)
            #pragma unroll
            for (int nt = 0; nt < 4; ++nt)
                #pragma unroll
                for (int c = 0; c < 4; ++c) {
                    int col = nt * 8 + 2 * q4 + (c & 1);  /* local in wn group */
                    float s = fmaf(2.f, acc[mt][nt][c], -wns[wn * 32 + col]);
                    int rr = mt * 2 + (c >> 1);
                    if (s > mx[rr]) mx[rr] = s;
                }
        #pragma unroll
        for (int rr = 0; rr < 4; ++rr)
            atomicMax(&rowbest[rloc[rr]], f2ord(mx[rr]));

        // relaxed threshold read (includes own update; staleness -> superset)
        int kc = kBase + ch * CBN + wn * 32;
        #pragma unroll
        for (int mt = 0; mt < 2; ++mt)
            #pragma unroll
            for (int hi = 0; hi < 2; ++hi) {
                int rr = mt * 2 + hi;
                float thr = ord2f(rowbest[rloc[rr]]) - delta[rr];
                if (mx[rr] < thr) continue;            /* fast skip */
                int row = rowBase + rloc[rr];
                #pragma unroll
                for (int nt = 0; nt < 4; ++nt)
                    #pragma unroll
                    for (int lo = 0; lo < 2; ++lo) {
                        int c = hi * 2 + lo;
                        int col = nt * 8 + 2 * q4 + lo;
                        float s = fmaf(2.f, acc[mt][nt][c], -wns[wn * 32 + col]);
                        if (s >= thr) {
                            int idx = atomicAdd(&g_ccnt[row], 1);
                            if (idx < CAP) g_cand[row * CAP + idx] = kc + col;
                        }
                    }
            }

        if (ch + 1 < NCH) CP_WAIT0();
        __syncthreads();
    }
}

// ---------------------------------------------------------------------------
// rescore (bit-exact reference arithmetic) + update, fused.
__global__ void hrq_rescore_update_kernel(const float* __restrict__ emb,
                                          float* __restrict__ out, int h) {
    __shared__ float rs[D_N];
    __shared__ unsigned long long wkey[4];
    __shared__ int swin;

    int b = blockIdx.x;
    int t = threadIdx.x;          // 128 threads
    int lane = t & 31, w = t >> 5;

    rs[t] = g_resid[(size_t)b * D_N + t];
    __syncthreads();

    int n = g_ccnt[b]; if (n > CAP) n = CAP; if (n < 1) n = 1;
    float R = g_rnorm[b];
    const float* __restrict__ Wh = emb + (size_t)h * K_N * D_N;
    const float* __restrict__ hw = g_wnorm + (size_t)h * K_N;

    unsigned long long best = 0ull;
    for (int i = t; i < n; i += 128) {
        int k = g_cand[b * CAP + i];
        const float4* wrow = (const float4*)(Wh + (size_t)k * D_N);
        float acc = 0.f;
        #pragma unroll
        for (int d4 = 0; d4 < D_N / 4; ++d4) {   // sequential ascending d
            float4 wv = __ldg(wrow + d4);
            acc = fmaf(rs[4 * d4],     wv.x, acc);
            acc = fmaf(rs[4 * d4 + 1], wv.y, acc);
            acc = fmaf(rs[4 * d4 + 2], wv.z, acc);
            acc = fmaf(rs[4 * d4 + 3], wv.w, acc);
        }
        float tt = __fsub_rn(__fadd_rn(R, hw[k]), 2.0f * acc);
        unsigned long long key =
            ((unsigned long long)f2ord(-tt) << 32) |
            (unsigned long long)(0xFFFFFFFFu - (unsigned)k);
        if (key > best) best = key;
    }
    #pragma unroll
    for (int off = 16; off; off >>= 1) {
        unsigned long long o = __shfl_xor_sync(0xffffffffu, best, off);
        if (o > best) best = o;
    }
    if (lane == 0) wkey[w] = best;
    __syncthreads();
    if (t == 0) {
        unsigned long long m = wkey[0];
        for (int i = 1; i < 4; ++i) if (wkey[i] > m) m = wkey[i];
        swin = (int)(0xFFFFFFFFu - (unsigned)(m & 0xFFFFFFFFull));
    }
    __syncthreads();

    int k = swin;
    float q  = Wh[(size_t)k * D_N + t];
    float nr = g_resid[(size_t)b * D_N + t] - q;
    g_resid[(size_t)b * D_N + t]   = nr;
    g_resid16[(size_t)b * D_N + t] = __float2bfloat16(nr);
    out[B_N + b * D_N + t] += q;
    __syncthreads();
    if (t < 32) {
        float s = warp_sumsq_128(g_resid + (size_t)b * D_N, t);
        if (t == 0) {
            g_rnorm[b] = s;
            out[B_N + B_N * D_N + b * H_N + h] = (float)k;
            g_ccnt[b] = 0;
        }
    }
}

// ---------------------------------------------------------------------------
extern "C" void kernel_launch(void* const* d_in, const int* in_sizes, int n_in,
                              void* d_out, int out_size) {
    const float* inputs = (const float*)d_in[0];
    const float* emb    = (const float*)d_in[1];
    if (n_in >= 2 && in_sizes[0] != B_N * D_N) {
        inputs = (const float*)d_in[1];
        emb    = (const float*)d_in[0];
    }
    float* out = (float*)d_out;

    cudaFuncSetAttribute(hrq_coarse_kernel,
                         cudaFuncAttributeMaxDynamicSharedMemorySize, SM_TOTAL);

    hrq_init_kernel<<<(B_N * D_N + 255) / 256, 256>>>(inputs, out);
    hrq_prep_kernel<<<(H_N * K_N * 32 + 255) / 256, 256>>>(emb);
    hrq_rnorm_kernel<<<(B_N * 32 + 255) / 256, 256>>>();

    dim3 cgrid(B_N / CBM, KSPLIT2);
    for (int h = 0; h < H_N; ++h) {
        hrq_coarse_kernel<<<cgrid, 256, SM_TOTAL>>>(h);
        hrq_rescore_update_kernel<<<B_N, 128>>>(emb, out, h);
    }
}

// round 9
// speedup vs baseline: 3.3928x; 1.1256x over previous
#include <cuda_runtime.h>
#include <cuda_bf16.h>
#include <cstdint>

#define B_N 4096
#define H_N 3
#define K_N 32768
#define D_N 128

#define CAP 256

/* coarse tiling */
#define CBM 128                 /* rows per CTA */
#define CBN 128                 /* codewords per chunk */
#define KSPLIT2 16
#define KN2 (K_N / KSPLIT2)     /* 2048 codewords per CTA */
#define NCH (KN2 / CBN)         /* 16 chunks */

#define APITCH 272              /* bytes per smem row: 256 + 16 pad */
#define BPITCH 272

/* smem layout (bytes) */
#define SM_A       0            /* 128 * 272 = 34816 */
#define SM_B0      34816        /* 128 * 272 = 34816 */
#define SM_B1      69632
#define SM_WNS0    104448       /* 128 floats */
#define SM_WNS1    104960
#define SM_ROWBEST 105472       /* 128 * 4 */
#define SM_TOTAL   105984

// ------------------------------ scratch ------------------------------------
__device__ float           g_resid[B_N * D_N];
__device__ __nv_bfloat16   g_resid16[B_N * D_N];
__device__ __nv_bfloat16   g_emb16[H_N * K_N * D_N];
__device__ float           g_wnorm[H_N * K_N];
__device__ unsigned        g_wnmax[H_N];
__device__ float           g_rnorm[B_N];
__device__ int             g_cand[B_N * CAP];
__device__ int             g_ccnt[B_N];

// ------------------------------ helpers ------------------------------------
__device__ __forceinline__ unsigned f2ord(float f) {
    unsigned u = __float_as_uint(f);
    return (u & 0x80000000u) ? ~u : (u | 0x80000000u);
}
__device__ __forceinline__ float ord2f(unsigned u) {
    return (u & 0x80000000u) ? __uint_as_float(u & 0x7FFFFFFFu)
                             : __uint_as_float(~u);
}
__device__ __forceinline__ uint32_t smem_u32(const void* p) {
    uint32_t a;
    asm("{ .reg .u64 t; cvta.to.shared.u64 t, %1; cvt.u32.u64 %0, t; }"
        : "=r"(a) : "l"(p));
    return a;
}
__device__ __forceinline__ void cp16(uint32_t dst, const void* src) {
    asm volatile("cp.async.ca.shared.global [%0], [%1], 16;"
                 :: "r"(dst), "l"(__cvta_generic_to_global(src)) : "memory");
}
#define CP_COMMIT() asm volatile("cp.async.commit_group;" ::: "memory")
#define CP_WAIT0()  asm volatile("cp.async.wait_group 0;" ::: "memory")

__device__ __forceinline__ void ldmx4(unsigned r[4], uint32_t addr) {
    asm volatile("ldmatrix.sync.aligned.m8n8.x4.shared.b16 {%0,%1,%2,%3}, [%4];"
                 : "=r"(r[0]), "=r"(r[1]), "=r"(r[2]), "=r"(r[3]) : "r"(addr));
}
__device__ __forceinline__ void mma16816(float c[4], const unsigned a[4],
                                         unsigned b0, unsigned b1) {
    asm("mma.sync.aligned.m16n8k16.row.col.f32.bf16.bf16.f32 "
        "{%0,%1,%2,%3},{%4,%5,%6,%7},{%8,%9},{%0,%1,%2,%3};"
        : "+f"(c[0]), "+f"(c[1]), "+f"(c[2]), "+f"(c[3])
        : "r"(a[0]), "r"(a[1]), "r"(a[2]), "r"(a[3]), "r"(b0), "r"(b1));
}

// XLA-GPU-style warp reduction of sum(x^2) over 128 floats (bit-exact w/ ref)
__device__ __forceinline__ float warp_sumsq_128(const float* __restrict__ x, int lane) {
    float acc = 0.f;
    #pragma unroll
    for (int i = 0; i < 4; ++i) {
        float v = x[lane + 32 * i];
        acc = __fadd_rn(acc, __fmul_rn(v, v));
    }
    #pragma unroll
    for (int off = 16; off; off >>= 1)
        acc = __fadd_rn(acc, __shfl_down_sync(0xffffffffu, acc, off));
    return acc;
}

// ---------------------------------------------------------------------------
__global__ void hrq_init_kernel(const float* __restrict__ inp, float* __restrict__ out) {
    int i = blockIdx.x * blockDim.x + threadIdx.x;
    if (i < B_N * D_N) {
        float v = inp[i];
        g_resid[i]   = v;
        g_resid16[i] = __float2bfloat16(v);
        out[B_N + i] = 0.f;
    }
    if (i < B_N) { out[i] = 0.f; g_ccnt[i] = 0; }
    if (i < H_N) g_wnmax[i] = 0u;
}

// emb -> bf16 copy + wnorm (+ per-head max), one warp per codeword
__global__ void hrq_prep_kernel(const float* __restrict__ emb) {
    int gw   = (blockIdx.x * blockDim.x + threadIdx.x) >> 5;
    int lane = threadIdx.x & 31;
    if (gw >= H_N * K_N) return;
    const float* x = emb + (size_t)gw * D_N;
    __nv_bfloat16* y = g_emb16 + (size_t)gw * D_N;
    float acc = 0.f;
    #pragma unroll
    for (int i = 0; i < 4; ++i) {
        float v = x[lane + 32 * i];
        y[lane + 32 * i] = __float2bfloat16(v);
        acc = __fadd_rn(acc, __fmul_rn(v, v));
    }
    #pragma unroll
    for (int off = 16; off; off >>= 1)
        acc = __fadd_rn(acc, __shfl_down_sync(0xffffffffu, acc, off));
    if (lane == 0) {
        g_wnorm[gw] = acc;
        atomicMax(&g_wnmax[gw / K_N], __float_as_uint(acc));
    }
}

__global__ void hrq_rnorm_kernel() {
    int gw   = (blockIdx.x * blockDim.x + threadIdx.x) >> 5;
    int lane = threadIdx.x & 31;
    if (gw >= B_N) return;
    float s = warp_sumsq_128(g_resid + (size_t)gw * D_N, lane);
    if (lane == 0) g_rnorm[gw] = s;
}

// ---------------------------------------------------------------------------
// coarse: bf16 mma.sync, warp tile 32x64, CBN=128 double-buffered via cp.async.
// Emits every codeword within delta of the (relaxed) running per-row best;
// delta = 2.5x the hard bf16 rounding bound, so the exact winner is always
// emitted (stale/partial thresholds only ADD candidates).
__global__ void __launch_bounds__(256, 2)
hrq_coarse_kernel(int h) {
    extern __shared__ char smem[];
    const uint32_t sb = smem_u32(smem);
    unsigned* rowbest = (unsigned*)(smem + SM_ROWBEST);

    const int tid  = threadIdx.x;
    const int lane = tid & 31;
    const int wid  = tid >> 5;
    const int wm   = wid & 3;           /* 4 row groups of 32 */
    const int wn   = wid >> 2;          /* 2 col groups of 64 */
    const int g4   = lane >> 2;         /* 0..7 */
    const int q4   = lane & 3;

    const int rowBase = blockIdx.x * CBM;
    const int kBase   = blockIdx.y * KN2;

    if (tid < 128) rowbest[tid] = 0u;

    const __nv_bfloat16* Wh = g_emb16 + ((size_t)h * K_N + kBase) * D_N;
    const float* hwg        = g_wnorm + (size_t)h * K_N + kBase;

    // stage A (128x128 bf16 -> padded smem rows)
    {
        const char* src = (const char*)(g_resid16 + (size_t)rowBase * D_N);
        #pragma unroll
        for (int j = 0; j < 8; ++j) {
            int i = tid + 256 * j, row = i >> 4, c = i & 15;
            cp16(sb + SM_A + row * APITCH + c * 16, src + i * 16);
        }
    }
    // stage B chunk 0 + wns0
    {
        const char* src = (const char*)Wh;
        #pragma unroll
        for (int j = 0; j < 8; ++j) {
            int i = tid + 256 * j, row = i >> 4, c = i & 15;
            cp16(sb + SM_B0 + row * BPITCH + c * 16, src + i * 16);
        }
        if (tid < 32) cp16(sb + SM_WNS0 + tid * 16, (const char*)hwg + tid * 16);
    }
    CP_COMMIT();

    // per-thread rows & deltas (4 result rows per thread)
    int rloc[4];
    float delta[4];
    {
        float wnmax = __uint_as_float(g_wnmax[h]);
        #pragma unroll
        for (int mt = 0; mt < 2; ++mt)
            #pragma unroll
            for (int hi = 0; hi < 2; ++hi) {
                int rr = mt * 2 + hi;
                rloc[rr] = wm * 32 + mt * 16 + hi * 8 + g4;
                float R = g_rnorm[rowBase + rloc[rr]];
                delta[rr] = 0.02f * sqrtf(R * wnmax);
            }
    }
    CP_WAIT0();
    __syncthreads();

    // ldmatrix lane-address components
    const int aRow = lane & 15;
    const int aCol = (lane >> 4) << 3;                    /* 0 or 8 */
    const int bN   = ((lane >= 16) ? 8 : 0) + (lane & 7);
    const int bK   = ((lane >> 3) & 1) << 3;

    for (int ch = 0; ch < NCH; ++ch) {
        const int cur = ch & 1;
        if (ch + 1 < NCH) {   // prefetch next B chunk into the other buffer
            const char* src = (const char*)(Wh + (size_t)(ch + 1) * CBN * D_N);
            uint32_t bdst = sb + (cur ? SM_B0 : SM_B1);
            #pragma unroll
            for (int j = 0; j < 8; ++j) {
                int i = tid + 256 * j, row = i >> 4, c = i & 15;
                cp16(bdst + row * BPITCH + c * 16, src + i * 16);
            }
            if (tid < 32)
                cp16(sb + (cur ? SM_WNS0 : SM_WNS1) + tid * 16,
                     (const char*)(hwg + (ch + 1) * CBN) + tid * 16);
            CP_COMMIT();
        }

        const uint32_t abase = sb + SM_A;
        const uint32_t bbase = sb + (cur ? SM_B1 : SM_B0);
        const float* wns = (const float*)(smem + (cur ? SM_WNS1 : SM_WNS0));

        float acc[2][8][4];
        #pragma unroll
        for (int mt = 0; mt < 2; ++mt)
            #pragma unroll
            for (int nt = 0; nt < 8; ++nt)
                #pragma unroll
                for (int c = 0; c < 4; ++c) acc[mt][nt][c] = 0.f;

        #pragma unroll
        for (int kt = 0; kt < 8; ++kt) {
            unsigned a0[4], a1[4], bf[4][4];
            ldmx4(a0, abase + (wm * 32 +      aRow) * APITCH + (kt * 16 + aCol) * 2);
            ldmx4(a1, abase + (wm * 32 + 16 + aRow) * APITCH + (kt * 16 + aCol) * 2);
            #pragma unroll
            for (int p = 0; p < 4; ++p)
                ldmx4(bf[p], bbase + (wn * 64 + p * 16 + bN) * BPITCH + (kt * 16 + bK) * 2);
            #pragma unroll
            for (int nt = 0; nt < 8; ++nt) {
                unsigned b0 = bf[nt >> 1][(nt & 1) * 2];
                unsigned b1 = bf[nt >> 1][(nt & 1) * 2 + 1];
                mma16816(acc[0][nt], a0, b0, b1);
                mma16816(acc[1][nt], a1, b0, b1);
            }
        }

        // per-row maxes of s = 2*acc - wn
        float mx[4] = { -3.4e38f, -3.4e38f, -3.4e38f, -3.4e38f };
        #pragma unroll
        for (int mt = 0; mt < 2; ++mt)
            #pragma unroll
            for (int nt = 0; nt < 8; ++nt)
                #pragma unroll
                for (int c = 0; c < 4; ++c) {
                    int col = nt * 8 + 2 * q4 + (c & 1);  /* local in wn group */
                    float s = fmaf(2.f, acc[mt][nt][c], -wns[wn * 64 + col]);
                    int rr = mt * 2 + (c >> 1);
                    if (s > mx[rr]) mx[rr] = s;
                }
        #pragma unroll
        for (int rr = 0; rr < 4; ++rr)
            atomicMax(&rowbest[rloc[rr]], f2ord(mx[rr]));

        // relaxed threshold read (includes own update; staleness -> superset)
        int kc = kBase + ch * CBN + wn * 64;
        #pragma unroll
        for (int mt = 0; mt < 2; ++mt)
            #pragma unroll
            for (int hi = 0; hi < 2; ++hi) {
                int rr = mt * 2 + hi;
                float thr = ord2f(rowbest[rloc[rr]]) - delta[rr];
                if (mx[rr] < thr) continue;            /* fast skip */
                int row = rowBase + rloc[rr];
                #pragma unroll
                for (int nt = 0; nt < 8; ++nt)
                    #pragma unroll
                    for (int lo = 0; lo < 2; ++lo) {
                        int c = hi * 2 + lo;
                        int col = nt * 8 + 2 * q4 + lo;
                        float s = fmaf(2.f, acc[mt][nt][c], -wns[wn * 64 + col]);
                        if (s >= thr) {
                            int idx = atomicAdd(&g_ccnt[row], 1);
                            if (idx < CAP) g_cand[row * CAP + idx] = kc + col;
                        }
                    }
            }

        if (ch + 1 < NCH) CP_WAIT0();
        __syncthreads();
    }
}

// ---------------------------------------------------------------------------
// rescore (bit-exact reference arithmetic) + update, fused.
__global__ void hrq_rescore_update_kernel(const float* __restrict__ emb,
                                          float* __restrict__ out, int h) {
    __shared__ float rs[D_N];
    __shared__ unsigned long long wkey[4];
    __shared__ int swin;

    int b = blockIdx.x;
    int t = threadIdx.x;          // 128 threads
    int lane = t & 31, w = t >> 5;

    rs[t] = g_resid[(size_t)b * D_N + t];
    __syncthreads();

    int n = g_ccnt[b]; if (n > CAP) n = CAP; if (n < 1) n = 1;
    float R = g_rnorm[b];
    const float* __restrict__ Wh = emb + (size_t)h * K_N * D_N;
    const float* __restrict__ hw = g_wnorm + (size_t)h * K_N;

    unsigned long long best = 0ull;
    for (int i = t; i < n; i += 128) {
        int k = g_cand[b * CAP + i];
        const float4* wrow = (const float4*)(Wh + (size_t)k * D_N);
        float acc = 0.f;
        #pragma unroll
        for (int d4 = 0; d4 < D_N / 4; ++d4) {   // sequential ascending d
            float4 wv = __ldg(wrow + d4);
            acc = fmaf(rs[4 * d4],     wv.x, acc);
            acc = fmaf(rs[4 * d4 + 1], wv.y, acc);
            acc = fmaf(rs[4 * d4 + 2], wv.z, acc);
            acc = fmaf(rs[4 * d4 + 3], wv.w, acc);
        }
        float tt = __fsub_rn(__fadd_rn(R, hw[k]), 2.0f * acc);
        unsigned long long key =
            ((unsigned long long)f2ord(-tt) << 32) |
            (unsigned long long)(0xFFFFFFFFu - (unsigned)k);
        if (key > best) best = key;
    }
    #pragma unroll
    for (int off = 16; off; off >>= 1) {
        unsigned long long o = __shfl_xor_sync(0xffffffffu, best, off);
        if (o > best) best = o;
    }
    if (lane == 0) wkey[w] = best;
    __syncthreads();
    if (t == 0) {
        unsigned long long m = wkey[0];
        for (int i = 1; i < 4; ++i) if (wkey[i] > m) m = wkey[i];
        swin = (int)(0xFFFFFFFFu - (unsigned)(m & 0xFFFFFFFFull));
    }
    __syncthreads();

    int k = swin;
    float q  = Wh[(size_t)k * D_N + t];
    float nr = g_resid[(size_t)b * D_N + t] - q;
    g_resid[(size_t)b * D_N + t]   = nr;
    g_resid16[(size_t)b * D_N + t] = __float2bfloat16(nr);
    out[B_N + b * D_N + t] += q;
    __syncthreads();
    if (t < 32) {
        float s = warp_sumsq_128(g_resid + (size_t)b * D_N, t);
        if (t == 0) {
            g_rnorm[b] = s;
            out[B_N + B_N * D_N + b * H_N + h] = (float)k;
            g_ccnt[b] = 0;
        }
    }
}

// ---------------------------------------------------------------------------
extern "C" void kernel_launch(void* const* d_in, const int* in_sizes, int n_in,
                              void* d_out, int out_size) {
    const float* inputs = (const float*)d_in[0];
    const float* emb    = (const float*)d_in[1];
    if (n_in >= 2 && in_sizes[0] != B_N * D_N) {
        inputs = (const float*)d_in[1];
        emb    = (const float*)d_in[0];
    }
    float* out = (float*)d_out;

    cudaFuncSetAttribute(hrq_coarse_kernel,
                         cudaFuncAttributeMaxDynamicSharedMemorySize, SM_TOTAL);

    hrq_init_kernel<<<(B_N * D_N + 255) / 256, 256>>>(inputs, out);
    hrq_prep_kernel<<<(H_N * K_N * 32 + 255) / 256, 256>>>(emb);
    hrq_rnorm_kernel<<<(B_N * 32 + 255) / 256, 256>>>();

    dim3 cgrid(B_N / CBM, KSPLIT2);
    for (int h = 0; h < H_N; ++h) {
        hrq_coarse_kernel<<<cgrid, 256, SM_TOTAL>>>(h);
        hrq_rescore_update_kernel<<<B_N, 128>>>(emb, out, h);
    }
}